// round 9
// baseline (speedup 1.0000x reference)
#include <cuda_runtime.h>
#include <cuda_bf16.h>
#include <cstdint>

#define NPIX   262144
#define CD     256
#define HW     16384
#define TILE_P 128
#define NTILES (NPIX / TILE_P)      // 2048
#define GRID   148
#define NTHR   512
#define INV_T  14.285714285714285f

// smem layout (bytes)
#define B_STRIDE 528                  // 132 words = 4 mod 32 banks: conflict-free ldsm
#define A_STRIDE 272                  // 68 words  = 4 mod 32 banks (128 px * 2B + pad)
#define OFF_B    0
#define OFF_A    (256 * B_STRIDE)     // 135168 ; A: [256 k][128 m] bf16, single buffer
#define OFF_LAB  (OFF_A + 256 * A_STRIDE)  // 204800 : 2 x (128 px * 32 bytes)
#define SMEM_SZ  (OFF_LAB + 2 * 4096)      // 212992

#define FIN_BLKS 512

__device__ float g_en[NTILES * 512];     // [tile][wn][row]  4MB
__device__ float g_ep[NTILES * 512];     // 4MB
__device__ float g_partial[FIN_BLKS];
__device__ int   g_pcnt[FIN_BLKS];

__device__ __forceinline__ uint32_t smem_u32(const void* p) {
    uint32_t a;
    asm("{ .reg .u64 t; cvta.to.shared.u64 t, %1; cvt.u32.u64 %0, t; }" : "=r"(a) : "l"(p));
    return a;
}
__device__ __forceinline__ void ldsm_x4(uint32_t* r, uint32_t addr) {
    asm volatile("ldmatrix.sync.aligned.m8n8.x4.shared.b16 {%0,%1,%2,%3}, [%4];"
                 : "=r"(r[0]), "=r"(r[1]), "=r"(r[2]), "=r"(r[3]) : "r"(addr));
}
__device__ __forceinline__ void ldsm_x4_t(uint32_t* r, uint32_t addr) {
    asm volatile("ldmatrix.sync.aligned.m8n8.x4.trans.shared.b16 {%0,%1,%2,%3}, [%4];"
                 : "=r"(r[0]), "=r"(r[1]), "=r"(r[2]), "=r"(r[3]) : "r"(addr));
}
__device__ __forceinline__ void mma_bf16(float* d, const uint32_t* a,
                                         uint32_t b0, uint32_t b1) {
    asm volatile(
        "mma.sync.aligned.m16n8k16.row.col.f32.bf16.bf16.f32 "
        "{%0,%1,%2,%3}, {%4,%5,%6,%7}, {%8,%9}, {%0,%1,%2,%3};"
        : "+f"(d[0]), "+f"(d[1]), "+f"(d[2]), "+f"(d[3])
        : "r"(a[0]), "r"(a[1]), "r"(a[2]), "r"(a[3]), "r"(b0), "r"(b1));
}
__device__ __forceinline__ unsigned mask8(const int4& v0, const int4& v1) {
    unsigned m = 0;
    m |= (v0.x != 0 ? 1u : 0u);
    m |= (v0.y != 0 ? 2u : 0u);
    m |= (v0.z != 0 ? 4u : 0u);
    m |= (v0.w != 0 ? 8u : 0u);
    m |= (v1.x != 0 ? 16u : 0u);
    m |= (v1.y != 0 ? 32u : 0u);
    m |= (v1.z != 0 ? 64u : 0u);
    m |= (v1.w != 0 ? 128u : 0u);
    return m;
}

// ===================== persistent fused main kernel =====================
// 148 CTAs x 512 thr (16 warps: wm 0..3 x wn 0..3), warp tile 32x64, block
// tile 128x256, K=256. A single-buffered, rotated per 64-channel k-group
// (barrier per group). Labels double-buffered. Epilogue warp-local.
__global__ void __launch_bounds__(NTHR, 1)
pcl_main(const float* __restrict__ feats, const float* __restrict__ queue,
         const int* __restrict__ labels)
{
    extern __shared__ char smem[];
    const uint32_t sb = smem_u32(smem);
    const int tid = threadIdx.x, lane = tid & 31, wid = tid >> 5;
    const int wm = wid >> 2, wn = wid & 3;
    const int bid = blockIdx.x;

    // ---- stage B once: queue fp32 -> bf16 [n][k] ----
    for (int i = tid; i < 256 * 128; i += NTHR) {
        int n = i >> 7, k2 = i & 127;
        float2 v = *(const float2*)(queue + n * 256 + k2 * 2);
        *(__nv_bfloat162*)(smem + OFF_B + n * B_STRIDE + k2 * 4) =
            __floats2bfloat162_rn(v.x, v.y);
    }
    // ---- stage first tile ----
    {
        const int n0 = bid * TILE_P;
        const float* fp = feats + (size_t)(n0 / HW) * CD * HW + (n0 % HW);
        for (int i = tid; i < 256 * 64; i += NTHR) {
            int row = i >> 6, p2 = i & 63;
            float2 v = *(const float2*)(fp + (size_t)row * HW + p2 * 2);
            *(__nv_bfloat162*)(smem + OFF_A + row * A_STRIDE + p2 * 4) =
                __floats2bfloat162_rn(v.x, v.y);
        }
        const int* lp = labels + (size_t)n0 * 256;
        for (int s = tid; s < 4096; s += NTHR) {
            int px = s >> 5, sub = s & 31;
            const int4* l4 = (const int4*)(lp + px * 256 + sub * 8);
            ((unsigned char*)(smem + OFF_LAB))[px * 32 + sub] =
                (unsigned char)mask8(l4[0], l4[1]);
        }
    }
    __syncthreads();

    // ldsm lane decomposition
    const int r8   = lane & 7;
    const int sel8 = (lane >> 3) & 1;
    const int selk = (lane >> 4) & 1;
    const uint32_t b_base = sb + OFF_B
        + (uint32_t)(wn * 64 + sel8 * 8 + r8) * B_STRIDE + (uint32_t)(selk * 8) * 2;
    const uint32_t a_base = sb + OFF_A
        + (uint32_t)(selk * 8 + r8) * A_STRIDE + (uint32_t)(wm * 32 + sel8 * 8) * 2;

    // prefetch decomposition (per k-group g):
    //  A: channels c = g*64 + (tid>>3), 8 threads/row, 4 float4 each
    //  labels: 2 slots of 32 classes: s = g*1024 + tid*2 + {0,1}
    const int pfc = tid >> 3;          // 0..63 channel within group
    const int pfq = tid & 7;           // float4 lane within row

    int p = 0;  // label buffer parity
#pragma unroll 1
    for (int cur = bid; cur < NTILES; cur += GRID, p ^= 1) {
        const int nxt = cur + GRID;
        const bool pf = nxt < NTILES;
        unsigned char* lmnxt = (unsigned char*)(smem + OFF_LAB + (p ^ 1) * 4096);
        const float* fnx = nullptr; const int* lnx = nullptr;
        if (pf) {
            const int nn0 = nxt * TILE_P;
            fnx = feats + (size_t)(nn0 / HW) * CD * HW + (nn0 % HW);
            lnx = labels + (size_t)nn0 * 256;
        }

        float acc[2][8][4];
#pragma unroll
        for (int mb = 0; mb < 2; mb++)
#pragma unroll
            for (int nb = 0; nb < 8; nb++)
#pragma unroll
                for (int e = 0; e < 4; e++) acc[mb][nb][e] = 0.0f;

#pragma unroll
        for (int g = 0; g < 4; g++) {
            // issue prefetch LDGs for k-group g of tile nxt
            float4 pa[4]; int4 pl[4];
            const int rowp = g * 64 + pfc;
            const int s0 = g * 1024 + tid * 2;
            const int px0 = s0 >> 5, sub0 = s0 & 31;
            const int px1 = (s0 + 1) >> 5, sub1 = (s0 + 1) & 31;
            if (pf) {
                const float4* asrc = (const float4*)(fnx + (size_t)rowp * HW);
#pragma unroll
                for (int i = 0; i < 4; i++) pa[i] = asrc[pfq + i * 8];
                const int4* ls0 = (const int4*)(lnx + px0 * 256 + sub0 * 8);
                const int4* ls1 = (const int4*)(lnx + px1 * 256 + sub1 * 8);
                pl[0] = ls0[0]; pl[1] = ls0[1];
                pl[2] = ls1[0]; pl[3] = ls1[1];
            }
            // 4 ksteps of mma on tile cur (k-group g)
#pragma unroll
            for (int kk = 0; kk < 4; kk++) {
                const int ks = g * 4 + kk;
                uint32_t a[2][4], bq[4][4];
                ldsm_x4_t(a[0], a_base + (uint32_t)ks * 16 * A_STRIDE);
                ldsm_x4_t(a[1], a_base + (uint32_t)ks * 16 * A_STRIDE + 32);
#pragma unroll
                for (int nbp = 0; nbp < 4; nbp++)
                    ldsm_x4(bq[nbp], b_base + (uint32_t)nbp * 16 * B_STRIDE + ks * 32);
#pragma unroll
                for (int mb = 0; mb < 2; mb++)
#pragma unroll
                    for (int nbp = 0; nbp < 4; nbp++) {
                        mma_bf16(acc[mb][2 * nbp],     a[mb], bq[nbp][0], bq[nbp][2]);
                        mma_bf16(acc[mb][2 * nbp + 1], a[mb], bq[nbp][1], bq[nbp][3]);
                    }
            }
            // labels: double-buffered, store now
            if (pf) {
                lmnxt[px0 * 32 + sub0] = (unsigned char)mask8(pl[0], pl[1]);
                lmnxt[px1 * 32 + sub1] = (unsigned char)mask8(pl[2], pl[3]);
            }
            __syncthreads();   // all warps done reading A k-group g of cur
            // overwrite A k-group g with tile nxt (read next at iter+1 group g,
            // which is separated from here by >=1 barrier)
            if (pf) {
#pragma unroll
                for (int i = 0; i < 4; i++) {
                    __nv_bfloat162 lo = __floats2bfloat162_rn(pa[i].x, pa[i].y);
                    __nv_bfloat162 hi = __floats2bfloat162_rn(pa[i].z, pa[i].w);
                    uint2 v = { *(uint32_t*)&lo, *(uint32_t*)&hi };
                    *(uint2*)(smem + OFF_A + rowp * A_STRIDE + (pfq + i * 8) * 8) = v;
                }
            }
        }

        // ---- epilogue tile cur: warp-local, no barrier ----
        const unsigned* labm = (const unsigned*)(smem + OFF_LAB + p * 4096);
#pragma unroll
        for (int mb = 0; mb < 2; mb++) {
#pragma unroll
            for (int half = 0; half < 2; half++) {
                const int row = wm * 32 + mb * 16 + (lane >> 2) + half * 8;
                const unsigned mw0 = labm[row * 8 + wn * 2];
                const unsigned mw1 = labm[row * 8 + wn * 2 + 1];
                float en = 0.0f, ep = 0.0f;
#pragma unroll
                for (int nb = 0; nb < 8; nb++) {
                    const unsigned mw = (nb < 4) ? mw0 : mw1;
                    const int bit0 = (nb & 3) * 8 + (lane & 3) * 2;
                    float l0 = acc[mb][nb][half * 2]     * INV_T;
                    float l1 = acc[mb][nb][half * 2 + 1] * INV_T;
                    bool y0 = (mw >> bit0) & 1u;
                    bool y1 = (mw >> (bit0 + 1)) & 1u;
                    float e0 = __expf(y0 ? -l0 : l0);
                    float e1 = __expf(y1 ? -l1 : l1);
                    en += y0 ? 0.0f : e0;  ep += y0 ? e0 : 0.0f;
                    en += y1 ? 0.0f : e1;  ep += y1 ? e1 : 0.0f;
                }
                en += __shfl_xor_sync(0xffffffffu, en, 1);
                en += __shfl_xor_sync(0xffffffffu, en, 2);
                ep += __shfl_xor_sync(0xffffffffu, ep, 1);
                ep += __shfl_xor_sync(0xffffffffu, ep, 2);
                if ((lane & 3) == 0) {   // deterministic per-(tile,wn,row) slots
                    const int slot = (cur * 4 + wn) * 128 + row;
                    g_en[slot] = en;
                    g_ep[slot] = ep;
                }
            }
        }
        // labels buffer flip is safe: lmnxt writes done before group-3 barrier;
        // labm(cur) reads done before next iteration's group-0 barrier, and the
        // next lmnxt writes target this iteration's labm only after that barrier
        // ... enforce with one barrier:
        __syncthreads();
    }
}

// ===================== finalize 1: combine wn partials, per-block reduce =====
__global__ void __launch_bounds__(512) pcl_fin1()
{
    __shared__ float ss[16];
    __shared__ int   sc[16];
    const int n = blockIdx.x * 512 + threadIdx.x;   // pixel id
    const int tile = n >> 7, row = n & 127;
    const int base = tile * 512 + row;
    float en = g_en[base] + g_en[base + 128] + g_en[base + 256] + g_en[base + 384];
    float ep = g_ep[base] + g_ep[base + 128] + g_ep[base + 256] + g_ep[base + 384];
    float loss = __logf(en * ep + 1.0f);
    int   cnt  = (loss != 0.0f) ? 1 : 0;
#pragma unroll
    for (int off = 16; off > 0; off >>= 1) {
        loss += __shfl_xor_sync(0xffffffffu, loss, off);
        cnt  += __shfl_xor_sync(0xffffffffu, cnt,  off);
    }
    const int lane = threadIdx.x & 31, wid = threadIdx.x >> 5;
    if (lane == 0) { ss[wid] = loss; sc[wid] = cnt; }
    __syncthreads();
    if (threadIdx.x == 0) {
        float s = 0.0f; int c = 0;
#pragma unroll
        for (int w = 0; w < 16; w++) { s += ss[w]; c += sc[w]; }
        g_partial[blockIdx.x] = s;
        g_pcnt[blockIdx.x]    = c;
    }
}

// ===================== finalize 2: scalar =====================
__global__ void __launch_bounds__(512) pcl_fin2(float* __restrict__ out)
{
    __shared__ float ss[16];
    __shared__ int   sc[16];
    float s = g_partial[threadIdx.x];
    int   c = g_pcnt[threadIdx.x];
#pragma unroll
    for (int off = 16; off > 0; off >>= 1) {
        s += __shfl_xor_sync(0xffffffffu, s, off);
        c += __shfl_xor_sync(0xffffffffu, c, off);
    }
    const int lane = threadIdx.x & 31, wid = threadIdx.x >> 5;
    if (lane == 0) { ss[wid] = s; sc[wid] = c; }
    __syncthreads();
    if (threadIdx.x == 0) {
        float t = 0.0f; int c2 = 0;
#pragma unroll
        for (int w = 0; w < 16; w++) { t += ss[w]; c2 += sc[w]; }
        out[0] = (c2 == 0) ? 0.0f : t / (float)(c2 < 1 ? 1 : c2);
    }
}

extern "C" void kernel_launch(void* const* d_in, const int* in_sizes, int n_in,
                              void* d_out, int out_size)
{
    const float* feats  = (const float*)d_in[0];
    const float* queue  = (const float*)d_in[1];
    const int*   labels = (const int*)d_in[2];
    float* out = (float*)d_out;

    static bool attr_set = false;
    if (!attr_set) {
        cudaFuncSetAttribute(pcl_main,
                             cudaFuncAttributeMaxDynamicSharedMemorySize, SMEM_SZ);
        attr_set = true;
    }

    pcl_main<<<GRID, NTHR, SMEM_SZ>>>(feats, queue, labels);
    pcl_fin1<<<FIN_BLKS, 512>>>();
    pcl_fin2<<<1, 512>>>(out);
}

// round 10
// speedup vs baseline: 1.3775x; 1.3775x over previous
#include <cuda_runtime.h>
#include <cuda_bf16.h>
#include <cstdint>

#define NPIX   262144
#define CD     256
#define HW     16384
#define TILE_P 64
#define NTILES (NPIX / TILE_P)      // 4096
#define GRID   148
#define NTHR   512
#define INV_T  14.285714285714285f

// smem layout (bytes)
#define B_STRIDE 528                  // 132 words = 4 mod 32 banks: conflict-free ldsm
#define A_STRIDE 144                  // 36 words  = 4 mod 32 banks
#define A_BUF    (256 * A_STRIDE)     // 36864
#define OFF_B    0
#define OFF_A    (256 * B_STRIDE)     // 135168
#define OFF_LAB  (OFF_A + 2 * A_BUF)  // 208896 : 2 x (64 px * 32 bytes)
#define SMEM_SZ  (OFF_LAB + 2 * 2048) // 212992

#define FIN_BLKS 512

__device__ float g_en[NTILES * 512];     // [tile][wn 0..7][row 0..63]  8MB
__device__ float g_ep[NTILES * 512];     // 8MB
__device__ float g_partial[FIN_BLKS];
__device__ int   g_pcnt[FIN_BLKS];

__device__ __forceinline__ uint32_t smem_u32(const void* p) {
    uint32_t a;
    asm("{ .reg .u64 t; cvta.to.shared.u64 t, %1; cvt.u32.u64 %0, t; }" : "=r"(a) : "l"(p));
    return a;
}
__device__ __forceinline__ void ldsm_x4(uint32_t* r, uint32_t addr) {
    asm volatile("ldmatrix.sync.aligned.m8n8.x4.shared.b16 {%0,%1,%2,%3}, [%4];"
                 : "=r"(r[0]), "=r"(r[1]), "=r"(r[2]), "=r"(r[3]) : "r"(addr));
}
__device__ __forceinline__ void ldsm_x4_t(uint32_t* r, uint32_t addr) {
    asm volatile("ldmatrix.sync.aligned.m8n8.x4.trans.shared.b16 {%0,%1,%2,%3}, [%4];"
                 : "=r"(r[0]), "=r"(r[1]), "=r"(r[2]), "=r"(r[3]) : "r"(addr));
}
__device__ __forceinline__ void mma_bf16(float* d, const uint32_t* a,
                                         uint32_t b0, uint32_t b1) {
    asm volatile(
        "mma.sync.aligned.m16n8k16.row.col.f32.bf16.bf16.f32 "
        "{%0,%1,%2,%3}, {%4,%5,%6,%7}, {%8,%9}, {%0,%1,%2,%3};"
        : "+f"(d[0]), "+f"(d[1]), "+f"(d[2]), "+f"(d[3])
        : "r"(a[0]), "r"(a[1]), "r"(a[2]), "r"(a[3]), "r"(b0), "r"(b1));
}
__device__ __forceinline__ unsigned mask8(const int4& v0, const int4& v1) {
    unsigned m = 0;
    m |= (v0.x != 0 ? 1u : 0u);
    m |= (v0.y != 0 ? 2u : 0u);
    m |= (v0.z != 0 ? 4u : 0u);
    m |= (v0.w != 0 ? 8u : 0u);
    m |= (v1.x != 0 ? 16u : 0u);
    m |= (v1.y != 0 ? 32u : 0u);
    m |= (v1.z != 0 ? 64u : 0u);
    m |= (v1.w != 0 ? 128u : 0u);
    return m;
}

// ===================== persistent fused main kernel =====================
// 148 CTAs x 512 thr (16 warps: wm 0..1 x wn 0..7), warp tile 32x32.
// Static schedule over 4096 tiles of 64 px; one __syncthreads per tile.
__global__ void __launch_bounds__(NTHR, 1)
pcl_main(const float* __restrict__ feats, const float* __restrict__ queue,
         const int* __restrict__ labels)
{
    extern __shared__ char smem[];
    const uint32_t sb = smem_u32(smem);
    const int tid = threadIdx.x, lane = tid & 31, wid = tid >> 5;
    const int wm = wid >> 3, wn = wid & 7;
    const int bid = blockIdx.x;

    // ---- stage B once: queue fp32 -> bf16 [n][k] ----
    for (int i = tid; i < 256 * 128; i += NTHR) {
        int n = i >> 7, k2 = i & 127;
        float2 v = *(const float2*)(queue + n * 256 + k2 * 2);
        *(__nv_bfloat162*)(smem + OFF_B + n * B_STRIDE + k2 * 4) =
            __floats2bfloat162_rn(v.x, v.y);
    }
    // ---- stage first tile (buf 0) ----
    {
        const int n0 = bid * TILE_P;
        const float* fp = feats + (size_t)(n0 / HW) * CD * HW + (n0 % HW);
        for (int i = tid; i < 256 * 32; i += NTHR) {
            int row = i >> 5, p2 = i & 31;
            float2 v = *(const float2*)(fp + (size_t)row * HW + p2 * 2);
            *(__nv_bfloat162*)(smem + OFF_A + row * A_STRIDE + p2 * 4) =
                __floats2bfloat162_rn(v.x, v.y);
        }
        const int* lp = labels + (size_t)n0 * 256;
        for (int s = tid; s < 2048; s += NTHR) {
            int px = s >> 5, sub = s & 31;
            const int4* l4 = (const int4*)(lp + px * 256 + sub * 8);
            ((unsigned char*)(smem + OFF_LAB))[px * 32 + sub] =
                (unsigned char)mask8(l4[0], l4[1]);
        }
    }
    __syncthreads();

    // ldsm lane decomposition
    const int r8   = lane & 7;
    const int sel8 = (lane >> 3) & 1;
    const int selk = (lane >> 4) & 1;
    const uint32_t b_base = sb + OFF_B
        + (uint32_t)(wn * 32 + sel8 * 8 + r8) * B_STRIDE + (uint32_t)(selk * 8) * 2;
    const uint32_t a_lane_off =
        (uint32_t)(selk * 8 + r8) * A_STRIDE + (uint32_t)(wm * 32 + sel8 * 8) * 2;

    int p = 0;  // buffer parity
#pragma unroll 1
    for (int cur = bid; cur < NTILES; cur += GRID, p ^= 1) {
        const int nxt = cur + GRID;
        const bool pf = nxt < NTILES;
        const uint32_t a_base = sb + OFF_A + (uint32_t)p * A_BUF + a_lane_off;
        char* anxt = smem + OFF_A + (p ^ 1) * A_BUF;
        unsigned char* lmnxt = (unsigned char*)(smem + OFF_LAB + (p ^ 1) * 2048);
        const float* fnx = nullptr; const int* lnx = nullptr;
        if (pf) {
            const int nn0 = nxt * TILE_P;
            fnx = feats + (size_t)(nn0 / HW) * CD * HW + (nn0 % HW);
            lnx = labels + (size_t)nn0 * 256;
        }

        float acc[2][4][4];
#pragma unroll
        for (int mb = 0; mb < 2; mb++)
#pragma unroll
            for (int nb = 0; nb < 4; nb++)
#pragma unroll
                for (int e = 0; e < 4; e++) acc[mb][nb][e] = 0.0f;

#pragma unroll
        for (int g = 0; g < 4; g++) {
            // prefetch tile nxt: A rows [g*64, g*64+64), label slots [g*512, g*512+512)
            float4 pa0, pa1; int4 pl0, pl1;
            const int rowp = g * 64 + (tid >> 3);
            const int q = tid & 7;
            const int slot = g * 512 + tid, pxl = slot >> 5, sub = slot & 31;
            if (pf) {
                const float4* asrc = (const float4*)(fnx + (size_t)rowp * HW);
                pa0 = asrc[q]; pa1 = asrc[q + 8];
                const int4* lsrc = (const int4*)(lnx + pxl * 256 + sub * 8);
                pl0 = lsrc[0]; pl1 = lsrc[1];
            }
            // 4 ksteps of mma on tile cur (k-group g)
#pragma unroll
            for (int kk = 0; kk < 4; kk++) {
                const int ks = g * 4 + kk;
                uint32_t a[2][4], bq[2][4];
                ldsm_x4_t(a[0], a_base + (uint32_t)ks * 16 * A_STRIDE);
                ldsm_x4_t(a[1], a_base + (uint32_t)ks * 16 * A_STRIDE + 32);
                ldsm_x4(bq[0], b_base + (uint32_t)ks * 32);
                ldsm_x4(bq[1], b_base + 16 * B_STRIDE + (uint32_t)ks * 32);
#pragma unroll
                for (int mb = 0; mb < 2; mb++)
#pragma unroll
                    for (int nbp = 0; nbp < 2; nbp++) {
                        mma_bf16(acc[mb][2 * nbp],     a[mb], bq[nbp][0], bq[nbp][2]);
                        mma_bf16(acc[mb][2 * nbp + 1], a[mb], bq[nbp][1], bq[nbp][3]);
                    }
            }
            // drain prefetch into nxt buffers
            if (pf) {
                __nv_bfloat162 lo0 = __floats2bfloat162_rn(pa0.x, pa0.y);
                __nv_bfloat162 hi0 = __floats2bfloat162_rn(pa0.z, pa0.w);
                uint2 v0 = { *(uint32_t*)&lo0, *(uint32_t*)&hi0 };
                *(uint2*)(anxt + rowp * A_STRIDE + q * 8) = v0;
                __nv_bfloat162 lo1 = __floats2bfloat162_rn(pa1.x, pa1.y);
                __nv_bfloat162 hi1 = __floats2bfloat162_rn(pa1.z, pa1.w);
                uint2 v1 = { *(uint32_t*)&lo1, *(uint32_t*)&hi1 };
                *(uint2*)(anxt + rowp * A_STRIDE + (q + 8) * 8) = v1;
                lmnxt[pxl * 32 + sub] = (unsigned char)mask8(pl0, pl1);
            }
        }

        // ---- epilogue tile cur: warp-local, no smem writes, no barrier ----
        const unsigned* labm = (const unsigned*)(smem + OFF_LAB + p * 2048);
#pragma unroll
        for (int mb = 0; mb < 2; mb++) {
#pragma unroll
            for (int half = 0; half < 2; half++) {
                const int row = wm * 32 + mb * 16 + (lane >> 2) + half * 8;
                const unsigned mw = labm[row * 8 + wn];   // 32 classes of this warp
                float en = 0.0f, ep = 0.0f;
#pragma unroll
                for (int nb = 0; nb < 4; nb++) {
                    const int bit0 = nb * 8 + (lane & 3) * 2;
                    float l0 = acc[mb][nb][half * 2]     * INV_T;
                    float l1 = acc[mb][nb][half * 2 + 1] * INV_T;
                    bool y0 = (mw >> bit0) & 1u;
                    bool y1 = (mw >> (bit0 + 1)) & 1u;
                    float e0 = __expf(y0 ? -l0 : l0);
                    float e1 = __expf(y1 ? -l1 : l1);
                    en += y0 ? 0.0f : e0;  ep += y0 ? e0 : 0.0f;
                    en += y1 ? 0.0f : e1;  ep += y1 ? e1 : 0.0f;
                }
                en += __shfl_xor_sync(0xffffffffu, en, 1);
                en += __shfl_xor_sync(0xffffffffu, en, 2);
                ep += __shfl_xor_sync(0xffffffffu, ep, 1);
                ep += __shfl_xor_sync(0xffffffffu, ep, 2);
                if ((lane & 3) == 0) {   // deterministic per-(tile,wn,row) slots
                    const int slot = cur * 512 + wn * 64 + row;
                    g_en[slot] = en;
                    g_ep[slot] = ep;
                }
            }
        }
        __syncthreads();   // flip double buffers
    }
}

// ===================== finalize 1: combine wn partials, per-block reduce =====
__global__ void __launch_bounds__(512) pcl_fin1()
{
    __shared__ float ss[16];
    __shared__ int   sc[16];
    const int n = blockIdx.x * 512 + threadIdx.x;   // pixel id
    const int tile = n >> 6, row = n & 63;
    const int base = tile * 512 + row;
    float en = 0.0f, ep = 0.0f;
#pragma unroll
    for (int w = 0; w < 8; w++) {
        en += g_en[base + w * 64];
        ep += g_ep[base + w * 64];
    }
    float loss = __logf(en * ep + 1.0f);
    int   cnt  = (loss != 0.0f) ? 1 : 0;
#pragma unroll
    for (int off = 16; off > 0; off >>= 1) {
        loss += __shfl_xor_sync(0xffffffffu, loss, off);
        cnt  += __shfl_xor_sync(0xffffffffu, cnt,  off);
    }
    const int lane = threadIdx.x & 31, wid = threadIdx.x >> 5;
    if (lane == 0) { ss[wid] = loss; sc[wid] = cnt; }
    __syncthreads();
    if (threadIdx.x == 0) {
        float s = 0.0f; int c = 0;
#pragma unroll
        for (int w = 0; w < 16; w++) { s += ss[w]; c += sc[w]; }
        g_partial[blockIdx.x] = s;
        g_pcnt[blockIdx.x]    = c;
    }
}

// ===================== finalize 2: scalar =====================
__global__ void __launch_bounds__(512) pcl_fin2(float* __restrict__ out)
{
    __shared__ float ss[16];
    __shared__ int   sc[16];
    float s = g_partial[threadIdx.x];
    int   c = g_pcnt[threadIdx.x];
#pragma unroll
    for (int off = 16; off > 0; off >>= 1) {
        s += __shfl_xor_sync(0xffffffffu, s, off);
        c += __shfl_xor_sync(0xffffffffu, c, off);
    }
    const int lane = threadIdx.x & 31, wid = threadIdx.x >> 5;
    if (lane == 0) { ss[wid] = s; sc[wid] = c; }
    __syncthreads();
    if (threadIdx.x == 0) {
        float t = 0.0f; int c2 = 0;
#pragma unroll
        for (int w = 0; w < 16; w++) { t += ss[w]; c2 += sc[w]; }
        out[0] = (c2 == 0) ? 0.0f : t / (float)(c2 < 1 ? 1 : c2);
    }
}

extern "C" void kernel_launch(void* const* d_in, const int* in_sizes, int n_in,
                              void* d_out, int out_size)
{
    const float* feats  = (const float*)d_in[0];
    const float* queue  = (const float*)d_in[1];
    const int*   labels = (const int*)d_in[2];
    float* out = (float*)d_out;

    static bool attr_set = false;
    if (!attr_set) {
        cudaFuncSetAttribute(pcl_main,
                             cudaFuncAttributeMaxDynamicSharedMemorySize, SMEM_SZ);
        attr_set = true;
    }

    pcl_main<<<GRID, NTHR, SMEM_SZ>>>(feats, queue, labels);
    pcl_fin1<<<FIN_BLKS, 512>>>();
    pcl_fin2<<<1, 512>>>(out);
}